// round 15
// baseline (speedup 1.0000x reference)
#include <cuda_runtime.h>
#include <cuda_fp16.h>
#include <cstdint>
#include <cstddef>

#define DEVI static __device__ __forceinline__

namespace li {

constexpr int B = 32, T = 1024, IN = 1024, OUT = 1024;
constexpr int TT = 128;                 // time rows per tile (GEMM M)
constexpr int TO = 128;                 // out cols per CTA   (GEMM N)
constexpr int BKH = 64;                 // halves per K slab (= one 128B row)
constexpr int SLABS = IN / BKH;         // 16
constexpr int TILES = T / TT;           // 8
constexpr int G = TILES * SLABS;        // 128 slabs per CTA
constexpr int TPS = TT / SLABS;         // 8 scan timesteps per slab

constexpr int STAGE_BYTES = (TT + TO) * 128;   // 32 KB (X 16K + W 16K, fp16)
constexpr int STG_STRIDE = 136;                // halves; conflict-free
constexpr int STAGING_OFF = 2 * STAGE_BYTES;   // 65536
constexpr int SMEM_DYN = STAGING_OFF + TT * STG_STRIDE * 2;  // 100352

__device__ __align__(16) __half g_Xh[(size_t)B * T * IN];   // 64MB scratch
__device__ __align__(16) __half g_Wh[(size_t)OUT * IN];     // 2MB scratch

DEVI uint32_t s2u(const void* p) {
  uint32_t a;
  asm("{ .reg .u64 t; cvta.to.shared.u64 t, %1; cvt.u32.u64 %0, t; }"
      : "=r"(a) : "l"(p));
  return a;
}
DEVI void cp16(uint32_t s, const void* g) {
  asm volatile("cp.async.cg.shared.global [%0], [%1], 16;" :: "r"(s), "l"(g)
               : "memory");
}
DEVI void cp_commit() { asm volatile("cp.async.commit_group;" ::: "memory"); }
DEVI void cp_wait0() { asm volatile("cp.async.wait_group 0;" ::: "memory"); }

DEVI void ldsm4(uint32_t* r, uint32_t a) {
  asm volatile("ldmatrix.sync.aligned.m8n8.x4.shared.b16 {%0,%1,%2,%3}, [%4];"
               : "=r"(r[0]), "=r"(r[1]), "=r"(r[2]), "=r"(r[3]) : "r"(a));
}
DEVI void mma16(float* c, const uint32_t* a, const uint32_t* b) {
  asm volatile(
      "mma.sync.aligned.m16n8k16.row.col.f32.f16.f16.f32 "
      "{%0,%1,%2,%3}, {%4,%5,%6,%7}, {%8,%9}, {%0,%1,%2,%3};"
      : "+f"(c[0]), "+f"(c[1]), "+f"(c[2]), "+f"(c[3])
      : "r"(a[0]), "r"(a[1]), "r"(a[2]), "r"(a[3]), "r"(b[0]), "r"(b[1]));
}
DEVI uint32_t packh2(float lo, float hi) {
  uint32_t d;
  asm("cvt.rn.f16x2.f32 %0, %1, %2;" : "=r"(d) : "f"(hi), "f"(lo));
  return d;
}
DEVI uint4 cvt8(float4 a, float4 b) {
  uint4 u;
  u.x = packh2(a.x, a.y);
  u.y = packh2(a.z, a.w);
  u.z = packh2(b.x, b.y);
  u.w = packh2(b.z, b.w);
  return u;
}

// ---------------- pre-pass: fp32 -> fp16 conversion (uint4 stores) -----------
__global__ void __launch_bounds__(256) cvt_kernel(const float4* __restrict__ X,
                                                  const float4* __restrict__ W) {
  const int64_t nx = (int64_t)B * T * IN / 8;  // 4194304 uint4 outputs
  const int64_t nw = (int64_t)OUT * IN / 8;    // 131072 uint4 outputs
  uint4* xo = reinterpret_cast<uint4*>(g_Xh);
  uint4* wo = reinterpret_cast<uint4*>(g_Wh);
  const int64_t stride = (int64_t)gridDim.x * blockDim.x;
  const int64_t t0 = (int64_t)blockIdx.x * blockDim.x + threadIdx.x;
#pragma unroll 4
  for (int64_t i = t0; i < nx; i += stride)
    xo[i] = cvt8(X[2 * i], X[2 * i + 1]);
  for (int64_t i = t0; i < nw; i += stride)
    wo[i] = cvt8(W[2 * i], W[2 * i + 1]);
}

// ---------------- main fused GEMM + slab-interleaved scan --------------------
// 128 threads, 4 warps 2x2, warp tile 64x64, kc-pipelined fragments.
// Tile t's scan runs 8 steps/slab inside tile t+1's slab loop (tensor shadow).
__global__ void __launch_bounds__(128, 2)
li_kernel(const float* __restrict__ bias, const float* __restrict__ decay,
          float* __restrict__ out) {
  extern __shared__ __align__(16) char dsm[];
  const uint32_t sbase = s2u(dsm);

  const int tid = threadIdx.x;
  const int wid = tid >> 5;
  const int lane = tid & 31;
  const int bb = blockIdx.x >> 3;
  const int o0 = (blockIdx.x & 7) * TO;

  // ---- scan state: every thread owns one o-channel ----
  const float dcy = decay[o0 + tid];
  const float omd = 1.0f - dcy;
  const float bo = bias[o0 + tid];
  float u = 0.f;
  const __half* sh = reinterpret_cast<const __half*>(dsm + STAGING_OFF);
  float* ob_base = out + (size_t)bb * T * OUT + o0 + tid;

  // ---- cp.async constants: 16 chunks of 16B per thread ----
  const int lr = tid >> 3;
  const int lc = tid & 7;
  const uint32_t sw_off = (uint32_t)lr * 128 + (uint32_t)((lc ^ (lr & 7)) << 4);
  const __half* Wg = g_Wh + (size_t)(o0 + lr) * IN + lc * 8;
  const __half* Xg0 = g_Xh + ((size_t)bb * T + lr) * IN + lc * 8;

  // ---- mma per-thread constants ----
  const int warp_m = wid >> 1, warp_n = wid & 1;
  const int r = lane & 7;
  const int khA = lane >> 4;
  const int khB = (lane >> 3) & 1;
  const uint32_t aBase =
      (uint32_t)(warp_m * 64 + ((lane >> 3) & 1) * 8 + r) * 128;
  const uint32_t bBase =
      (uint32_t)(TT * 128) +
      (uint32_t)(warp_n * 64 + ((lane >> 4) << 3) + r) * 128;

  float acc[4][8][4];

  auto load_slab = [&](int g) {
    const int t0 = (g >> 4) * TT;
    const int k0 = (g & 15) * BKH;
    const uint32_t sb = sbase + (uint32_t)(g & 1) * STAGE_BYTES;
    const __half* Xg = Xg0 + (size_t)t0 * IN + k0;
    const __half* Ws = Wg + k0;
#pragma unroll
    for (int i = 0; i < 8; ++i)
      cp16(sb + sw_off + (uint32_t)i * 2048, Xg + (size_t)i * 16 * IN);
#pragma unroll
    for (int i = 0; i < 8; ++i)
      cp16(sb + (uint32_t)(TT * 128) + sw_off + (uint32_t)i * 2048,
           Ws + (size_t)i * 16 * IN);
  };

  // scan chunk: TPS steps of tile `st`'s staging (t index base = ks*TPS)
  auto scan_chunk = [&](int st, int ks) {
    float* ob = ob_base + (size_t)(st * TT + ks * TPS) * OUT;
#pragma unroll
    for (int t = 0; t < TPS; ++t) {
      const float x =
          __half2float(sh[(ks * TPS + t) * STG_STRIDE + tid]) + bo;
      u = fmaf(dcy, u, omd * x);
      ob[(size_t)t * OUT] = u;
    }
  };

  int g = 0;
  load_slab(0);
  cp_commit();

  for (int tile = 0; tile < TILES; ++tile) {
#pragma unroll
    for (int mf = 0; mf < 4; ++mf)
#pragma unroll
      for (int nf = 0; nf < 8; ++nf)
#pragma unroll
        for (int j = 0; j < 4; ++j) acc[mf][nf][j] = 0.f;

    for (int ks = 0; ks < SLABS; ++ks) {
      cp_wait0();
      __syncthreads();
      const uint32_t sb = sbase + (uint32_t)(g & 1) * STAGE_BYTES;

      // ---- kc-pipelined fragment loads + MMAs ----
      uint32_t A[2][4][4], Bf[2][4][4];
      {
        const uint32_t swA = (uint32_t)((khA ^ r) << 4);
        const uint32_t swB = (uint32_t)((khB ^ r) << 4);
#pragma unroll
        for (int mf = 0; mf < 4; ++mf)
          ldsm4(A[0][mf], sb + aBase + (uint32_t)mf * 2048 + swA);
#pragma unroll
        for (int p = 0; p < 4; ++p)
          ldsm4(Bf[0][p], sb + bBase + (uint32_t)p * 2048 + swB);
      }
      if (g + 1 < G) {
        load_slab(g + 1);
        cp_commit();
      }
#pragma unroll
      for (int kc = 0; kc < 4; ++kc) {
        const int pb = kc & 1;
        if (kc < 3) {
          const uint32_t swA = (uint32_t)(((2 * (kc + 1) + khA) ^ r) << 4);
          const uint32_t swB = (uint32_t)(((2 * (kc + 1) + khB) ^ r) << 4);
#pragma unroll
          for (int mf = 0; mf < 4; ++mf)
            ldsm4(A[pb ^ 1][mf], sb + aBase + (uint32_t)mf * 2048 + swA);
#pragma unroll
          for (int p = 0; p < 4; ++p)
            ldsm4(Bf[pb ^ 1][p], sb + bBase + (uint32_t)p * 2048 + swB);
        }
#pragma unroll
        for (int mf = 0; mf < 4; ++mf)
#pragma unroll
          for (int nf = 0; nf < 8; ++nf)
            mma16(acc[mf][nf], A[pb][mf], &Bf[pb][nf >> 1][(nf & 1) * 2]);
      }
      // ---- interleaved scan of previous tile (LDS+FFMA+STG only) ----
      if (tile > 0) scan_chunk(tile - 1, ks);
      ++g;
    }

    // ---- epilogue: fragments -> fp16 staging [t][o] ----
    __syncthreads();  // last scan chunk's staging reads precede overwrite
    unsigned* stg_u = reinterpret_cast<unsigned*>(dsm + STAGING_OFF);
#pragma unroll
    for (int mf = 0; mf < 4; ++mf)
#pragma unroll
      for (int nf = 0; nf < 8; ++nf) {
        const int row = warp_m * 64 + mf * 16 + (lane >> 2);
        const int col = warp_n * 64 + nf * 8 + 2 * (lane & 3);
        stg_u[(row * STG_STRIDE + col) >> 1] =
            packh2(acc[mf][nf][0], acc[mf][nf][1]);
        stg_u[((row + 8) * STG_STRIDE + col) >> 1] =
            packh2(acc[mf][nf][2], acc[mf][nf][3]);
      }
    __syncthreads();
  }

  // ---- standalone scan of the final tile ----
  for (int ks = 0; ks < SLABS; ++ks) scan_chunk(TILES - 1, ks);
}

}  // namespace li

extern "C" void kernel_launch(void* const* d_in, const int* in_sizes, int n_in,
                              void* d_out, int out_size) {
  const float* X = (const float*)d_in[0];      // [B,T,IN]
  const float* W = (const float*)d_in[1];      // [OUT,IN]
  const float* bias = (const float*)d_in[2];   // [OUT]
  const float* decay = (const float*)d_in[3];  // [OUT]
  float* out = (float*)d_out;                  // [B,T,OUT]

  static bool init = false;
  if (!init) {
    cudaFuncSetAttribute(li::li_kernel,
                         cudaFuncAttributeMaxDynamicSharedMemorySize,
                         li::SMEM_DYN);
    init = true;
  }
  li::cvt_kernel<<<1184, 256>>>((const float4*)X, (const float4*)W);
  li::li_kernel<<<li::B * (li::OUT / li::TO), 128, li::SMEM_DYN>>>(bias, decay,
                                                                   out);
}

// round 16
// speedup vs baseline: 1.1436x; 1.1436x over previous
#include <cuda_runtime.h>
#include <cuda_fp16.h>
#include <cstdint>
#include <cstddef>

#define DEVI static __device__ __forceinline__

namespace li {

constexpr int B = 32, T = 1024, IN = 1024, OUT = 1024;
constexpr int TT = 128;                 // time rows per tile (GEMM M)
constexpr int TO = 128;                 // out cols per CTA   (GEMM N)
constexpr int BKH = 64;                 // halves per K slab (= one 128B row)
constexpr int SLABS = IN / BKH;         // 16
constexpr int TILES = T / TT;           // 8
constexpr int G = TILES * SLABS;        // 128 slabs per CTA

constexpr int STAGE_BYTES = (TT + TO) * 128;   // 32 KB (X 16K + W 16K, fp16)
constexpr int STG_STRIDE = 136;                // halves; conflict-free
constexpr int STAGING_OFF = 2 * STAGE_BYTES;   // 65536
constexpr int SMEM_DYN = STAGING_OFF + TT * STG_STRIDE * 2;  // 100352

__device__ __align__(16) __half g_Xh[(size_t)B * T * IN];   // 64MB scratch
__device__ __align__(16) __half g_Wh[(size_t)OUT * IN];     // 2MB scratch

DEVI uint32_t s2u(const void* p) {
  uint32_t a;
  asm("{ .reg .u64 t; cvta.to.shared.u64 t, %1; cvt.u32.u64 %0, t; }"
      : "=r"(a) : "l"(p));
  return a;
}
DEVI void cp16(uint32_t s, const void* g) {
  asm volatile("cp.async.cg.shared.global [%0], [%1], 16;" :: "r"(s), "l"(g)
               : "memory");
}
DEVI void cp_commit() { asm volatile("cp.async.commit_group;" ::: "memory"); }
DEVI void cp_wait0() { asm volatile("cp.async.wait_group 0;" ::: "memory"); }

DEVI void ldsm4(uint32_t* r, uint32_t a) {
  asm volatile("ldmatrix.sync.aligned.m8n8.x4.shared.b16 {%0,%1,%2,%3}, [%4];"
               : "=r"(r[0]), "=r"(r[1]), "=r"(r[2]), "=r"(r[3]) : "r"(a));
}
DEVI void mma16(float* c, const uint32_t* a, const uint32_t* b) {
  asm volatile(
      "mma.sync.aligned.m16n8k16.row.col.f32.f16.f16.f32 "
      "{%0,%1,%2,%3}, {%4,%5,%6,%7}, {%8,%9}, {%0,%1,%2,%3};"
      : "+f"(c[0]), "+f"(c[1]), "+f"(c[2]), "+f"(c[3])
      : "r"(a[0]), "r"(a[1]), "r"(a[2]), "r"(a[3]), "r"(b[0]), "r"(b[1]));
}
DEVI uint32_t packh2(float lo, float hi) {
  uint32_t d;
  asm("cvt.rn.f16x2.f32 %0, %1, %2;" : "=r"(d) : "f"(hi), "f"(lo));
  return d;
}
DEVI uint4 cvt8(float4 a, float4 b) {
  uint4 u;
  u.x = packh2(a.x, a.y);
  u.y = packh2(a.z, a.w);
  u.z = packh2(b.x, b.y);
  u.w = packh2(b.z, b.w);
  return u;
}

// ---------------- pre-pass: fp32 -> fp16, exact-cover fully unrolled ---------
// 2048 blocks x 256 threads = 524288 threads.
// X: 4194304 uint4 outputs = exactly 8 per thread (wave-strided, coalesced).
// W: 131072 uint4 outputs = 1 for each of the first 131072 threads.
__global__ void __launch_bounds__(256) cvt_kernel(const float4* __restrict__ X,
                                                  const float4* __restrict__ W) {
  uint4* xo = reinterpret_cast<uint4*>(g_Xh);
  uint4* wo = reinterpret_cast<uint4*>(g_Wh);
  const int gtid = blockIdx.x * 256 + threadIdx.x;   // 0..524287
#pragma unroll
  for (int it = 0; it < 8; ++it) {
    const size_t i = (size_t)it * 524288 + (size_t)gtid;
    xo[i] = cvt8(X[2 * i], X[2 * i + 1]);
  }
  if (gtid < 131072) {
    const size_t i = (size_t)gtid;
    wo[i] = cvt8(W[2 * i], W[2 * i + 1]);
  }
}

// ---------------- main fused GEMM + leaky-integrator scan (R8, proven) -------
// 128 threads, 4 warps in 2x2 grid, warp tile 64x64, kc-pipelined fragments.
__global__ void __launch_bounds__(128, 2)
li_kernel(const float* __restrict__ bias, const float* __restrict__ decay,
          float* __restrict__ out) {
  extern __shared__ __align__(16) char dsm[];
  const uint32_t sbase = s2u(dsm);

  const int tid = threadIdx.x;
  const int wid = tid >> 5;
  const int lane = tid & 31;
  const int bb = blockIdx.x >> 3;
  const int o0 = (blockIdx.x & 7) * TO;

  // ---- scan state: every thread owns one o-channel ----
  const float dcy = decay[o0 + tid];
  const float omd = 1.0f - dcy;
  const float bo = bias[o0 + tid];
  float u = 0.f;

  // ---- cp.async constants: 16 chunks of 16B per thread ----
  const int lr = tid >> 3;
  const int lc = tid & 7;
  const uint32_t sw_off = (uint32_t)lr * 128 + (uint32_t)((lc ^ (lr & 7)) << 4);
  const __half* Wg = g_Wh + (size_t)(o0 + lr) * IN + lc * 8;
  const __half* Xg0 = g_Xh + ((size_t)bb * T + lr) * IN + lc * 8;

  // ---- mma per-thread constants ----
  const int warp_m = wid >> 1, warp_n = wid & 1;
  const int r = lane & 7;
  const int khA = lane >> 4;
  const int khB = (lane >> 3) & 1;
  const uint32_t aBase =
      (uint32_t)(warp_m * 64 + ((lane >> 3) & 1) * 8 + r) * 128;
  const uint32_t bBase =
      (uint32_t)(TT * 128) +
      (uint32_t)(warp_n * 64 + ((lane >> 4) << 3) + r) * 128;

  float acc[4][8][4];

  auto load_slab = [&](int g) {
    const int t0 = (g >> 4) * TT;
    const int k0 = (g & 15) * BKH;
    const uint32_t sb = sbase + (uint32_t)(g & 1) * STAGE_BYTES;
    const __half* Xg = Xg0 + (size_t)t0 * IN + k0;
    const __half* Ws = Wg + k0;
#pragma unroll
    for (int i = 0; i < 8; ++i)
      cp16(sb + sw_off + (uint32_t)i * 2048, Xg + (size_t)i * 16 * IN);
#pragma unroll
    for (int i = 0; i < 8; ++i)
      cp16(sb + (uint32_t)(TT * 128) + sw_off + (uint32_t)i * 2048,
           Ws + (size_t)i * 16 * IN);
  };

  int g = 0;
  load_slab(0);
  cp_commit();

  for (int tile = 0; tile < TILES; ++tile) {
#pragma unroll
    for (int mf = 0; mf < 4; ++mf)
#pragma unroll
      for (int nf = 0; nf < 8; ++nf)
#pragma unroll
        for (int j = 0; j < 4; ++j) acc[mf][nf][j] = 0.f;

    for (int ks = 0; ks < SLABS; ++ks) {
      cp_wait0();
      __syncthreads();
      const uint32_t sb = sbase + (uint32_t)(g & 1) * STAGE_BYTES;

      // ---- kc-pipelined fragment loads + MMAs ----
      uint32_t A[2][4][4], Bf[2][4][4];
      // preload kc=0 fragments first (before the cp.async issue burst)
      {
        const uint32_t swA = (uint32_t)((khA ^ r) << 4);
        const uint32_t swB = (uint32_t)((khB ^ r) << 4);
#pragma unroll
        for (int mf = 0; mf < 4; ++mf)
          ldsm4(A[0][mf], sb + aBase + (uint32_t)mf * 2048 + swA);
#pragma unroll
        for (int p = 0; p < 4; ++p)
          ldsm4(Bf[0][p], sb + bBase + (uint32_t)p * 2048 + swB);
      }
      // issue next slab's loads while kc=0 fragments are in flight
      if (g + 1 < G) {
        load_slab(g + 1);
        cp_commit();
      }
#pragma unroll
      for (int kc = 0; kc < 4; ++kc) {
        const int pb = kc & 1;
        if (kc < 3) {  // prefetch next phase's fragments
          const uint32_t swA = (uint32_t)(((2 * (kc + 1) + khA) ^ r) << 4);
          const uint32_t swB = (uint32_t)(((2 * (kc + 1) + khB) ^ r) << 4);
#pragma unroll
          for (int mf = 0; mf < 4; ++mf)
            ldsm4(A[pb ^ 1][mf], sb + aBase + (uint32_t)mf * 2048 + swA);
#pragma unroll
          for (int p = 0; p < 4; ++p)
            ldsm4(Bf[pb ^ 1][p], sb + bBase + (uint32_t)p * 2048 + swB);
        }
#pragma unroll
        for (int mf = 0; mf < 4; ++mf)
#pragma unroll
          for (int nf = 0; nf < 8; ++nf)
            mma16(acc[mf][nf], A[pb][mf], &Bf[pb][nf >> 1][(nf & 1) * 2]);
      }
      ++g;
    }

    // ---- epilogue: fragments -> fp16 staging [t][o] ----
    unsigned* stg_u = reinterpret_cast<unsigned*>(dsm + STAGING_OFF);
#pragma unroll
    for (int mf = 0; mf < 4; ++mf)
#pragma unroll
      for (int nf = 0; nf < 8; ++nf) {
        const int row = warp_m * 64 + mf * 16 + (lane >> 2);
        const int col = warp_n * 64 + nf * 8 + 2 * (lane & 3);
        stg_u[(row * STG_STRIDE + col) >> 1] =
            packh2(acc[mf][nf][0], acc[mf][nf][1]);
        stg_u[((row + 8) * STG_STRIDE + col) >> 1] =
            packh2(acc[mf][nf][2], acc[mf][nf][3]);
      }
    __syncthreads();

    // ---- fused leaky-integrator scan; carry u persists across tiles ----
    {
      const __half* sh = reinterpret_cast<const __half*>(dsm + STAGING_OFF);
      float* ob = out + ((size_t)bb * T + tile * TT) * OUT + o0 + tid;
#pragma unroll 8
      for (int t = 0; t < TT; ++t) {
        const float x = __half2float(sh[t * STG_STRIDE + tid]) + bo;
        u = fmaf(dcy, u, omd * x);
        ob[(size_t)t * OUT] = u;
      }
    }
  }
}

}  // namespace li

extern "C" void kernel_launch(void* const* d_in, const int* in_sizes, int n_in,
                              void* d_out, int out_size) {
  const float* X = (const float*)d_in[0];      // [B,T,IN]
  const float* W = (const float*)d_in[1];      // [OUT,IN]
  const float* bias = (const float*)d_in[2];   // [OUT]
  const float* decay = (const float*)d_in[3];  // [OUT]
  float* out = (float*)d_out;                  // [B,T,OUT]

  static bool init = false;
  if (!init) {
    cudaFuncSetAttribute(li::li_kernel,
                         cudaFuncAttributeMaxDynamicSharedMemorySize,
                         li::SMEM_DYN);
    init = true;
  }
  li::cvt_kernel<<<2048, 256>>>((const float4*)X, (const float4*)W);
  li::li_kernel<<<li::B * (li::OUT / li::TO), 128, li::SMEM_DYN>>>(bias, decay,
                                                                   out);
}